// round 1
// baseline (speedup 1.0000x reference)
#include <cuda_runtime.h>
#include <cuda_bf16.h>
#include <math.h>

// Problem constants
#define BATCH 4
#define SEQ   2048
#define HDIM  1024
#define FDIM  4096
#define NH    8
#define DH    128            // head dim
#define MROWS (BATCH*SEQ)    // 8192
#define SCALE 11.313708498984760f  // sqrt(128)  (faithful bug: multiply by sqrt(d))

// GEMM tiling
#define BM 128
#define BN 128
#define BK 16
#define TM 8
#define TN 8
#define NTHREADS 256

// ---------------------------------------------------------------------------
// Scratch (device globals; no allocation allowed)
// ---------------------------------------------------------------------------
__device__ float g_q  [(size_t)MROWS * HDIM];
__device__ float g_k  [(size_t)MROWS * HDIM];
__device__ float g_v  [(size_t)MROWS * HDIM];
__device__ float g_ctx[(size_t)MROWS * HDIM];
__device__ float g_tmp[(size_t)MROWS * HDIM];   // attn_out, then ffn2
__device__ float g_y1 [(size_t)MROWS * HDIM];   // LN1 output
__device__ float g_ffn[(size_t)MROWS * FDIM];   // relu(y1@W1+b1)
__device__ float g_scores[(size_t)BATCH * NH * SEQ * SEQ]; // 512 MB

// ---------------------------------------------------------------------------
// Core 128x128 fp32 block GEMM.  NT=false: C = A[MxK] * B[KxN]
//                                NT=true : C = A[MxK] * B[NxK]^T
// Caller pre-offsets A,B,C,bias to the tile origin. Dims assumed divisible.
// ---------------------------------------------------------------------------
template <bool NT>
__device__ __forceinline__ void gemm_block(
    const float* __restrict__ A, int lda,
    const float* __restrict__ B, int ldb,
    float* __restrict__ C, int ldc,
    int K, float alpha, const float* __restrict__ bias, int relu)
{
    __shared__ float As[BK][BM];
    __shared__ float Bs[BK][BN];

    const int tid = threadIdx.x;
    const int tx  = tid % 16;       // column group
    const int ty  = tid / 16;       // row group

    const int arow = tid / 4;       // 0..63  (tile rows, +64 second)
    const int acol = tid % 4;       // float4 index along K (0..3)
    const int brow = tid / 32;      // 0..7   (k rows for NN B load)
    const int bcol = tid % 32;      // float4 index along N

    float acc[TM][TN];
    #pragma unroll
    for (int i = 0; i < TM; i++)
        #pragma unroll
        for (int j = 0; j < TN; j++) acc[i][j] = 0.0f;

    for (int k0 = 0; k0 < K; k0 += BK) {
        // Load A tile (transposed into As[k][m])
        #pragma unroll
        for (int r = 0; r < 2; r++) {
            int row = arow + r * 64;
            float4 t = *reinterpret_cast<const float4*>(
                A + (size_t)row * lda + k0 + acol * 4);
            As[acol*4+0][row] = t.x;
            As[acol*4+1][row] = t.y;
            As[acol*4+2][row] = t.z;
            As[acol*4+3][row] = t.w;
        }
        if (NT) {
            // B is [N x K] row-major: same pattern as A, transposed into Bs[k][n]
            #pragma unroll
            for (int r = 0; r < 2; r++) {
                int row = arow + r * 64;   // n index
                float4 t = *reinterpret_cast<const float4*>(
                    B + (size_t)row * ldb + k0 + acol * 4);
                Bs[acol*4+0][row] = t.x;
                Bs[acol*4+1][row] = t.y;
                Bs[acol*4+2][row] = t.z;
                Bs[acol*4+3][row] = t.w;
            }
        } else {
            // B is [K x N] row-major: direct float4 into Bs[k][n]
            #pragma unroll
            for (int r = 0; r < 2; r++) {
                int row = brow + r * 8;    // k index
                float4 t = *reinterpret_cast<const float4*>(
                    B + (size_t)(k0 + row) * ldb + bcol * 4);
                *reinterpret_cast<float4*>(&Bs[row][bcol*4]) = t;
            }
        }
        __syncthreads();

        #pragma unroll
        for (int k = 0; k < BK; k++) {
            float ra[TM], rb[TN];
            *reinterpret_cast<float4*>(&ra[0]) = *reinterpret_cast<const float4*>(&As[k][ty*TM]);
            *reinterpret_cast<float4*>(&ra[4]) = *reinterpret_cast<const float4*>(&As[k][ty*TM+4]);
            *reinterpret_cast<float4*>(&rb[0]) = *reinterpret_cast<const float4*>(&Bs[k][tx*TN]);
            *reinterpret_cast<float4*>(&rb[4]) = *reinterpret_cast<const float4*>(&Bs[k][tx*TN+4]);
            #pragma unroll
            for (int i = 0; i < TM; i++)
                #pragma unroll
                for (int j = 0; j < TN; j++)
                    acc[i][j] += ra[i] * rb[j];
        }
        __syncthreads();
    }

    // Epilogue
    #pragma unroll
    for (int i = 0; i < TM; i++) {
        int row = ty * TM + i;
        #pragma unroll
        for (int j = 0; j < TN; j += 4) {
            int col = tx * TN + j;
            float4 v;
            v.x = acc[i][j+0] * alpha;
            v.y = acc[i][j+1] * alpha;
            v.z = acc[i][j+2] * alpha;
            v.w = acc[i][j+3] * alpha;
            if (bias) {
                v.x += bias[col+0]; v.y += bias[col+1];
                v.z += bias[col+2]; v.w += bias[col+3];
            }
            if (relu) {
                v.x = fmaxf(v.x, 0.f); v.y = fmaxf(v.y, 0.f);
                v.z = fmaxf(v.z, 0.f); v.w = fmaxf(v.w, 0.f);
            }
            *reinterpret_cast<float4*>(C + (size_t)row * ldc + col) = v;
        }
    }
}

// ---------------------------------------------------------------------------
// Dense (non-batched) NN GEMM:  C[MxN] = A[MxK] @ B[KxN]  (+bias)(+relu)
// ---------------------------------------------------------------------------
__global__ __launch_bounds__(NTHREADS)
void k_gemm_nn(const float* __restrict__ A, const float* __restrict__ B,
               float* __restrict__ C, int K,
               int lda, int ldb, int ldc,
               const float* __restrict__ bias, int relu, float alpha)
{
    const size_t m0 = (size_t)blockIdx.y * BM;
    const size_t n0 = (size_t)blockIdx.x * BN;
    gemm_block<false>(A + m0 * lda, lda,
                      B + n0, ldb,
                      C + m0 * ldc + n0, ldc,
                      K, alpha, bias ? bias + n0 : nullptr, relu);
}

// ---------------------------------------------------------------------------
// Attention scores: per (b,h): S = (Qbh @ Kbh^T) * sqrt(d)
// ---------------------------------------------------------------------------
__global__ __launch_bounds__(NTHREADS)
void k_scores(const float* __restrict__ Q, const float* __restrict__ Km,
              float* __restrict__ Sc)
{
    const int z = blockIdx.z;
    const int b = z / NH, h = z % NH;
    const size_t base = (size_t)b * SEQ * HDIM + (size_t)h * DH;
    const float* A = Q  + base + (size_t)blockIdx.y * BM * HDIM;
    const float* B = Km + base + (size_t)blockIdx.x * BN * HDIM;
    float* C = Sc + (size_t)z * SEQ * SEQ
                  + (size_t)blockIdx.y * BM * SEQ + (size_t)blockIdx.x * BN;
    gemm_block<true>(A, HDIM, B, HDIM, C, SEQ, DH, SCALE, nullptr, 0);
}

// ---------------------------------------------------------------------------
// ctx = attn @ Vbh  (per (b,h); N = DH = 128 = one tile column)
// ---------------------------------------------------------------------------
__global__ __launch_bounds__(NTHREADS)
void k_ctx(const float* __restrict__ Sc, const float* __restrict__ V,
           float* __restrict__ Ctx)
{
    const int z = blockIdx.z;
    const int b = z / NH, h = z % NH;
    const size_t base = (size_t)b * SEQ * HDIM + (size_t)h * DH;
    const float* A = Sc + (size_t)z * SEQ * SEQ + (size_t)blockIdx.y * BM * SEQ;
    const float* B = V + base;
    float* C = Ctx + base + (size_t)blockIdx.y * BM * HDIM;
    gemm_block<false>(A, SEQ, B, HDIM, C, HDIM, SEQ, 1.0f, nullptr, 0);
}

// ---------------------------------------------------------------------------
// Row softmax with additive padding mask (mask==1 -> -1e9)
// One block per row of scores; row length SEQ=2048.
// ---------------------------------------------------------------------------
__global__ __launch_bounds__(256)
void k_softmax(float* __restrict__ Sc, const float* __restrict__ mask)
{
    const int rowid = blockIdx.x;          // 0 .. B*NH*SEQ-1
    const int b = rowid / (NH * SEQ);
    float* p = Sc + (size_t)rowid * SEQ;
    const float* mrow = mask + (size_t)b * SEQ;

    __shared__ float buf[SEQ];
    __shared__ float red[256];
    const int tid = threadIdx.x;

    float lmax = -INFINITY;
    #pragma unroll
    for (int t = tid; t < SEQ; t += 256) {
        float v = p[t] + mrow[t] * (-1e9f);
        buf[t] = v;
        lmax = fmaxf(lmax, v);
    }
    red[tid] = lmax; __syncthreads();
    #pragma unroll
    for (int s = 128; s > 0; s >>= 1) {
        if (tid < s) red[tid] = fmaxf(red[tid], red[tid + s]);
        __syncthreads();
    }
    const float m = red[0];
    __syncthreads();

    float lsum = 0.0f;
    #pragma unroll
    for (int t = tid; t < SEQ; t += 256) {
        float e = __expf(buf[t] - m);
        buf[t] = e;
        lsum += e;
    }
    red[tid] = lsum; __syncthreads();
    #pragma unroll
    for (int s = 128; s > 0; s >>= 1) {
        if (tid < s) red[tid] += red[tid + s];
        __syncthreads();
    }
    const float inv = 1.0f / red[0];
    #pragma unroll
    for (int t = tid; t < SEQ; t += 256) p[t] = buf[t] * inv;
}

// ---------------------------------------------------------------------------
// out = LayerNorm(a + b) * gamma + beta   (row width HDIM=1024)
// ---------------------------------------------------------------------------
__global__ __launch_bounds__(256)
void k_ln(const float* __restrict__ a, const float* __restrict__ bb,
          const float* __restrict__ gamma, const float* __restrict__ beta,
          float* __restrict__ out)
{
    const int row = blockIdx.x;
    const float* pa = a  + (size_t)row * HDIM;
    const float* pb = bb + (size_t)row * HDIM;
    float* po = out + (size_t)row * HDIM;
    const int tid = threadIdx.x;

    float vals[4];
    float s = 0.f, sq = 0.f;
    #pragma unroll
    for (int i = 0; i < 4; i++) {
        int c = tid + i * 256;
        float v = pa[c] + pb[c];
        vals[i] = v; s += v; sq += v * v;
    }
    __shared__ float r1[256], r2[256];
    r1[tid] = s; r2[tid] = sq; __syncthreads();
    #pragma unroll
    for (int st = 128; st > 0; st >>= 1) {
        if (tid < st) { r1[tid] += r1[tid + st]; r2[tid] += r2[tid + st]; }
        __syncthreads();
    }
    const float mu  = r1[0] * (1.0f / HDIM);
    const float var = r2[0] * (1.0f / HDIM) - mu * mu;
    const float inv = rsqrtf(var + 1e-6f);
    #pragma unroll
    for (int i = 0; i < 4; i++) {
        int c = tid + i * 256;
        po[c] = (vals[i] - mu) * inv * gamma[c] + beta[c];
    }
}

// ---------------------------------------------------------------------------
// Launch
// ---------------------------------------------------------------------------
extern "C" void kernel_launch(void* const* d_in, const int* in_sizes, int n_in,
                              void* d_out, int out_size)
{
    const float* x     = (const float*)d_in[0];
    const float* mask  = (const float*)d_in[1];
    const float* Wq    = (const float*)d_in[2];
    const float* Wk    = (const float*)d_in[3];
    const float* Wv    = (const float*)d_in[4];
    const float* Wo    = (const float*)d_in[5];
    const float* W1    = (const float*)d_in[6];
    const float* b1    = (const float*)d_in[7];
    const float* W2    = (const float*)d_in[8];
    const float* b2    = (const float*)d_in[9];
    const float* gamma = (const float*)d_in[10];
    const float* beta  = (const float*)d_in[11];
    float* out = (float*)d_out;

    float *q, *k, *v, *ctx, *tmp, *y1, *ffn, *sc;
    cudaGetSymbolAddress((void**)&q,   g_q);
    cudaGetSymbolAddress((void**)&k,   g_k);
    cudaGetSymbolAddress((void**)&v,   g_v);
    cudaGetSymbolAddress((void**)&ctx, g_ctx);
    cudaGetSymbolAddress((void**)&tmp, g_tmp);
    cudaGetSymbolAddress((void**)&y1,  g_y1);
    cudaGetSymbolAddress((void**)&ffn, g_ffn);
    cudaGetSymbolAddress((void**)&sc,  g_scores);

    const dim3 gProj(HDIM / BN, MROWS / BM);   // 8 x 64
    const dim3 gFfn1(FDIM / BN, MROWS / BM);   // 32 x 64

    // QKV projections
    k_gemm_nn<<<gProj, NTHREADS>>>(x, Wq, q, HDIM, HDIM, HDIM, HDIM, nullptr, 0, 1.0f);
    k_gemm_nn<<<gProj, NTHREADS>>>(x, Wk, k, HDIM, HDIM, HDIM, HDIM, nullptr, 0, 1.0f);
    k_gemm_nn<<<gProj, NTHREADS>>>(x, Wv, v, HDIM, HDIM, HDIM, HDIM, nullptr, 0, 1.0f);

    // scores = Q K^T * sqrt(d)   (batched over 32 (b,h))
    k_scores<<<dim3(SEQ / BN, SEQ / BM, BATCH * NH), NTHREADS>>>(q, k, sc);

    // softmax with mask
    k_softmax<<<BATCH * NH * SEQ, 256>>>(sc, mask);

    // ctx = attn @ V
    k_ctx<<<dim3(1, SEQ / BM, BATCH * NH), NTHREADS>>>(sc, v, ctx);

    // attn_out = ctx @ Wo
    k_gemm_nn<<<gProj, NTHREADS>>>(ctx, Wo, tmp, HDIM, HDIM, HDIM, HDIM, nullptr, 0, 1.0f);

    // y1 = LN(x + attn_out)
    k_ln<<<MROWS, 256>>>(x, tmp, gamma, beta, y1);

    // ffn = relu(y1 @ W1 + b1)
    k_gemm_nn<<<gFfn1, NTHREADS>>>(y1, W1, ffn, HDIM, HDIM, FDIM, FDIM, b1, 1, 1.0f);

    // tmp = ffn @ W2 + b2
    k_gemm_nn<<<gProj, NTHREADS>>>(ffn, W2, tmp, FDIM, FDIM, HDIM, HDIM, b2, 0, 1.0f);

    // out = LN(y1 + tmp)
    k_ln<<<MROWS, 256>>>(y1, tmp, gamma, beta, out);
}

// round 5
// speedup vs baseline: 1.0006x; 1.0006x over previous
#include <cuda_runtime.h>
#include <cuda_bf16.h>
#include <math.h>

// Problem constants
#define BATCH 4
#define SEQ   2048
#define HDIM  1024
#define FDIM  4096
#define NH    8
#define DH    128            // head dim
#define MROWS (BATCH*SEQ)    // 8192
#define SCALE 11.313708498984760f  // sqrt(128)  (faithful bug: multiply by sqrt(d))

// GEMM tiling
#define BM 128
#define BN 128
#define BK 16
#define TM 8
#define TN 8
#define NTHREADS 256

// ---------------------------------------------------------------------------
// Scratch (device globals; no allocation allowed)
// ---------------------------------------------------------------------------
__device__ float g_q  [(size_t)MROWS * HDIM];
__device__ float g_k  [(size_t)MROWS * HDIM];
__device__ float g_v  [(size_t)MROWS * HDIM];
__device__ float g_ctx[(size_t)MROWS * HDIM];
__device__ float g_tmp[(size_t)MROWS * HDIM];   // attn_out, then ffn2
__device__ float g_y1 [(size_t)MROWS * HDIM];   // LN1 output
__device__ float g_ffn[(size_t)MROWS * FDIM];   // relu(y1@W1+b1)
__device__ float g_scores[(size_t)BATCH * NH * SEQ * SEQ]; // 512 MB

// ---------------------------------------------------------------------------
// Core 128x128 fp32 block GEMM.  NT=false: C = A[MxK] * B[KxN]
//                                NT=true : C = A[MxK] * B[NxK]^T
// Caller pre-offsets A,B,C,bias to the tile origin. Dims assumed divisible.
// ---------------------------------------------------------------------------
template <bool NT>
__device__ __forceinline__ void gemm_block(
    const float* __restrict__ A, int lda,
    const float* __restrict__ B, int ldb,
    float* __restrict__ C, int ldc,
    int K, float alpha, const float* __restrict__ bias, int relu)
{
    __shared__ float As[BK][BM];
    __shared__ float Bs[BK][BN];

    const int tid = threadIdx.x;
    const int tx  = tid % 16;       // column group
    const int ty  = tid / 16;       // row group

    const int arow = tid / 4;       // 0..63  (tile rows, +64 second)
    const int acol = tid % 4;       // float4 index along K (0..3)
    const int brow = tid / 32;      // 0..7   (k rows for NN B load)
    const int bcol = tid % 32;      // float4 index along N

    float acc[TM][TN];
    #pragma unroll
    for (int i = 0; i < TM; i++)
        #pragma unroll
        for (int j = 0; j < TN; j++) acc[i][j] = 0.0f;

    for (int k0 = 0; k0 < K; k0 += BK) {
        // Load A tile (transposed into As[k][m])
        #pragma unroll
        for (int r = 0; r < 2; r++) {
            int row = arow + r * 64;
            float4 t = *reinterpret_cast<const float4*>(
                A + (size_t)row * lda + k0 + acol * 4);
            As[acol*4+0][row] = t.x;
            As[acol*4+1][row] = t.y;
            As[acol*4+2][row] = t.z;
            As[acol*4+3][row] = t.w;
        }
        if (NT) {
            // B is [N x K] row-major: same pattern as A, transposed into Bs[k][n]
            #pragma unroll
            for (int r = 0; r < 2; r++) {
                int row = arow + r * 64;   // n index
                float4 t = *reinterpret_cast<const float4*>(
                    B + (size_t)row * ldb + k0 + acol * 4);
                Bs[acol*4+0][row] = t.x;
                Bs[acol*4+1][row] = t.y;
                Bs[acol*4+2][row] = t.z;
                Bs[acol*4+3][row] = t.w;
            }
        } else {
            // B is [K x N] row-major: direct float4 into Bs[k][n]
            #pragma unroll
            for (int r = 0; r < 2; r++) {
                int row = brow + r * 8;    // k index
                float4 t = *reinterpret_cast<const float4*>(
                    B + (size_t)(k0 + row) * ldb + bcol * 4);
                *reinterpret_cast<float4*>(&Bs[row][bcol*4]) = t;
            }
        }
        __syncthreads();

        #pragma unroll
        for (int k = 0; k < BK; k++) {
            float ra[TM], rb[TN];
            *reinterpret_cast<float4*>(&ra[0]) = *reinterpret_cast<const float4*>(&As[k][ty*TM]);
            *reinterpret_cast<float4*>(&ra[4]) = *reinterpret_cast<const float4*>(&As[k][ty*TM+4]);
            *reinterpret_cast<float4*>(&rb[0]) = *reinterpret_cast<const float4*>(&Bs[k][tx*TN]);
            *reinterpret_cast<float4*>(&rb[4]) = *reinterpret_cast<const float4*>(&Bs[k][tx*TN+4]);
            #pragma unroll
            for (int i = 0; i < TM; i++)
                #pragma unroll
                for (int j = 0; j < TN; j++)
                    acc[i][j] += ra[i] * rb[j];
        }
        __syncthreads();
    }

    // Epilogue
    #pragma unroll
    for (int i = 0; i < TM; i++) {
        int row = ty * TM + i;
        #pragma unroll
        for (int j = 0; j < TN; j += 4) {
            int col = tx * TN + j;
            float4 v;
            v.x = acc[i][j+0] * alpha;
            v.y = acc[i][j+1] * alpha;
            v.z = acc[i][j+2] * alpha;
            v.w = acc[i][j+3] * alpha;
            if (bias) {
                v.x += bias[col+0]; v.y += bias[col+1];
                v.z += bias[col+2]; v.w += bias[col+3];
            }
            if (relu) {
                v.x = fmaxf(v.x, 0.f); v.y = fmaxf(v.y, 0.f);
                v.z = fmaxf(v.z, 0.f); v.w = fmaxf(v.w, 0.f);
            }
            *reinterpret_cast<float4*>(C + (size_t)row * ldc + col) = v;
        }
    }
}

// ---------------------------------------------------------------------------
// Dense (non-batched) NN GEMM:  C[MxN] = A[MxK] @ B[KxN]  (+bias)(+relu)
// ---------------------------------------------------------------------------
__global__ __launch_bounds__(NTHREADS)
void k_gemm_nn(const float* __restrict__ A, const float* __restrict__ B,
               float* __restrict__ C, int K,
               int lda, int ldb, int ldc,
               const float* __restrict__ bias, int relu, float alpha)
{
    const size_t m0 = (size_t)blockIdx.y * BM;
    const size_t n0 = (size_t)blockIdx.x * BN;
    gemm_block<false>(A + m0 * lda, lda,
                      B + n0, ldb,
                      C + m0 * ldc + n0, ldc,
                      K, alpha, bias ? bias + n0 : nullptr, relu);
}

// ---------------------------------------------------------------------------
// Attention scores: per (b,h): S = (Qbh @ Kbh^T) * sqrt(d)
// ---------------------------------------------------------------------------
__global__ __launch_bounds__(NTHREADS)
void k_scores(const float* __restrict__ Q, const float* __restrict__ Km,
              float* __restrict__ Sc)
{
    const int z = blockIdx.z;
    const int b = z / NH, h = z % NH;
    const size_t base = (size_t)b * SEQ * HDIM + (size_t)h * DH;
    const float* A = Q  + base + (size_t)blockIdx.y * BM * HDIM;
    const float* B = Km + base + (size_t)blockIdx.x * BN * HDIM;
    float* C = Sc + (size_t)z * SEQ * SEQ
                  + (size_t)blockIdx.y * BM * SEQ + (size_t)blockIdx.x * BN;
    gemm_block<true>(A, HDIM, B, HDIM, C, SEQ, DH, SCALE, nullptr, 0);
}

// ---------------------------------------------------------------------------
// ctx = attn @ Vbh  (per (b,h); N = DH = 128 = one tile column)
// ---------------------------------------------------------------------------
__global__ __launch_bounds__(NTHREADS)
void k_ctx(const float* __restrict__ Sc, const float* __restrict__ V,
           float* __restrict__ Ctx)
{
    const int z = blockIdx.z;
    const int b = z / NH, h = z % NH;
    const size_t base = (size_t)b * SEQ * HDIM + (size_t)h * DH;
    const float* A = Sc + (size_t)z * SEQ * SEQ + (size_t)blockIdx.y * BM * SEQ;
    const float* B = V + base;
    float* C = Ctx + base + (size_t)blockIdx.y * BM * HDIM;
    gemm_block<false>(A, SEQ, B, HDIM, C, HDIM, SEQ, 1.0f, nullptr, 0);
}

// ---------------------------------------------------------------------------
// Row softmax with additive padding mask (mask==1 -> -1e9)
// One block per row of scores; row length SEQ=2048.
// ---------------------------------------------------------------------------
__global__ __launch_bounds__(256)
void k_softmax(float* __restrict__ Sc, const float* __restrict__ mask)
{
    const int rowid = blockIdx.x;          // 0 .. B*NH*SEQ-1
    const int b = rowid / (NH * SEQ);
    float* p = Sc + (size_t)rowid * SEQ;
    const float* mrow = mask + (size_t)b * SEQ;

    __shared__ float buf[SEQ];
    __shared__ float red[256];
    const int tid = threadIdx.x;

    float lmax = -INFINITY;
    #pragma unroll
    for (int t = tid; t < SEQ; t += 256) {
        float v = p[t] + mrow[t] * (-1e9f);
        buf[t] = v;
        lmax = fmaxf(lmax, v);
    }
    red[tid] = lmax; __syncthreads();
    #pragma unroll
    for (int s = 128; s > 0; s >>= 1) {
        if (tid < s) red[tid] = fmaxf(red[tid], red[tid + s]);
        __syncthreads();
    }
    const float m = red[0];
    __syncthreads();

    float lsum = 0.0f;
    #pragma unroll
    for (int t = tid; t < SEQ; t += 256) {
        float e = __expf(buf[t] - m);
        buf[t] = e;
        lsum += e;
    }
    red[tid] = lsum; __syncthreads();
    #pragma unroll
    for (int s = 128; s > 0; s >>= 1) {
        if (tid < s) red[tid] += red[tid + s];
        __syncthreads();
    }
    const float inv = 1.0f / red[0];
    #pragma unroll
    for (int t = tid; t < SEQ; t += 256) p[t] = buf[t] * inv;
}

// ---------------------------------------------------------------------------
// out = LayerNorm(a + b) * gamma + beta   (row width HDIM=1024)
// ---------------------------------------------------------------------------
__global__ __launch_bounds__(256)
void k_ln(const float* __restrict__ a, const float* __restrict__ bb,
          const float* __restrict__ gamma, const float* __restrict__ beta,
          float* __restrict__ out)
{
    const int row = blockIdx.x;
    const float* pa = a  + (size_t)row * HDIM;
    const float* pb = bb + (size_t)row * HDIM;
    float* po = out + (size_t)row * HDIM;
    const int tid = threadIdx.x;

    float vals[4];
    float s = 0.f, sq = 0.f;
    #pragma unroll
    for (int i = 0; i < 4; i++) {
        int c = tid + i * 256;
        float v = pa[c] + pb[c];
        vals[i] = v; s += v; sq += v * v;
    }
    __shared__ float r1[256], r2[256];
    r1[tid] = s; r2[tid] = sq; __syncthreads();
    #pragma unroll
    for (int st = 128; st > 0; st >>= 1) {
        if (tid < st) { r1[tid] += r1[tid + st]; r2[tid] += r2[tid + st]; }
        __syncthreads();
    }
    const float mu  = r1[0] * (1.0f / HDIM);
    const float var = r2[0] * (1.0f / HDIM) - mu * mu;
    const float inv = rsqrtf(var + 1e-6f);
    #pragma unroll
    for (int i = 0; i < 4; i++) {
        int c = tid + i * 256;
        po[c] = (vals[i] - mu) * inv * gamma[c] + beta[c];
    }
}

// ---------------------------------------------------------------------------
// Launch
// ---------------------------------------------------------------------------
extern "C" void kernel_launch(void* const* d_in, const int* in_sizes, int n_in,
                              void* d_out, int out_size)
{
    const float* x     = (const float*)d_in[0];
    const float* mask  = (const float*)d_in[1];
    const float* Wq    = (const float*)d_in[2];
    const float* Wk    = (const float*)d_in[3];
    const float* Wv    = (const float*)d_in[4];
    const float* Wo    = (const float*)d_in[5];
    const float* W1    = (const float*)d_in[6];
    const float* b1    = (const float*)d_in[7];
    const float* W2    = (const float*)d_in[8];
    const float* b2    = (const float*)d_in[9];
    const float* gamma = (const float*)d_in[10];
    const float* beta  = (const float*)d_in[11];
    float* out = (float*)d_out;

    float *q, *k, *v, *ctx, *tmp, *y1, *ffn, *sc;
    cudaGetSymbolAddress((void**)&q,   g_q);
    cudaGetSymbolAddress((void**)&k,   g_k);
    cudaGetSymbolAddress((void**)&v,   g_v);
    cudaGetSymbolAddress((void**)&ctx, g_ctx);
    cudaGetSymbolAddress((void**)&tmp, g_tmp);
    cudaGetSymbolAddress((void**)&y1,  g_y1);
    cudaGetSymbolAddress((void**)&ffn, g_ffn);
    cudaGetSymbolAddress((void**)&sc,  g_scores);

    const dim3 gProj(HDIM / BN, MROWS / BM);   // 8 x 64
    const dim3 gFfn1(FDIM / BN, MROWS / BM);   // 32 x 64

    // QKV projections
    k_gemm_nn<<<gProj, NTHREADS>>>(x, Wq, q, HDIM, HDIM, HDIM, HDIM, nullptr, 0, 1.0f);
    k_gemm_nn<<<gProj, NTHREADS>>>(x, Wk, k, HDIM, HDIM, HDIM, HDIM, nullptr, 0, 1.0f);
    k_gemm_nn<<<gProj, NTHREADS>>>(x, Wv, v, HDIM, HDIM, HDIM, HDIM, nullptr, 0, 1.0f);

    // scores = Q K^T * sqrt(d)   (batched over 32 (b,h))
    k_scores<<<dim3(SEQ / BN, SEQ / BM, BATCH * NH), NTHREADS>>>(q, k, sc);

    // softmax with mask
    k_softmax<<<BATCH * NH * SEQ, 256>>>(sc, mask);

    // ctx = attn @ V
    k_ctx<<<dim3(1, SEQ / BM, BATCH * NH), NTHREADS>>>(sc, v, ctx);

    // attn_out = ctx @ Wo
    k_gemm_nn<<<gProj, NTHREADS>>>(ctx, Wo, tmp, HDIM, HDIM, HDIM, HDIM, nullptr, 0, 1.0f);

    // y1 = LN(x + attn_out)
    k_ln<<<MROWS, 256>>>(x, tmp, gamma, beta, y1);

    // ffn = relu(y1 @ W1 + b1)
    k_gemm_nn<<<gFfn1, NTHREADS>>>(y1, W1, ffn, HDIM, HDIM, FDIM, FDIM, b1, 1, 1.0f);

    // tmp = ffn @ W2 + b2
    k_gemm_nn<<<gProj, NTHREADS>>>(ffn, W2, tmp, FDIM, FDIM, HDIM, HDIM, b2, 0, 1.0f);

    // out = LN(y1 + tmp)
    k_ln<<<MROWS, 256>>>(y1, tmp, gamma, beta, out);
}